// round 2
// baseline (speedup 1.0000x reference)
#include <cuda_runtime.h>

// Problem constants
#define L_SEQ  16384
#define H_DIM  1024
#define P_DIM  256
#define PP_DIM 512          // 2*P : [re | im] planes
#define NCHUNK 128
#define S_CHUNK 128         // L = NCHUNK * S_CHUNK

// ----------------------------------------------------------------------------
// Device scratch (static globals; no cudaMalloc allowed)
// ----------------------------------------------------------------------------
__device__ float  g_X[(size_t)L_SEQ * PP_DIM];   // Bu -> xs, in place (33.5 MB)
__device__ float  g_Bb[PP_DIM * H_DIM];          // [Bb_re rows 0..255 | Bb_im rows 256..511] x H
__device__ float  g_C2[H_DIM * PP_DIM];          // rows h: [2*Cr(h,p) | -2*Ci(h,p)]
__device__ float2 g_lam[P_DIM];                  // Lambda_bar
__device__ float2 g_gamma[P_DIM];                // (Lambda_bar - 1)/Lambda
__device__ float2 g_lamS[P_DIM];                 // Lambda_bar^S (exact, via exp)
__device__ float2 g_b[NCHUNK][P_DIM];            // per-chunk local finals
__device__ float2 g_pref[NCHUNK][P_DIM];         // carry entering each chunk

// ----------------------------------------------------------------------------
// prep: Lambda_bar, gamma, lam^S.  Matches jax's fp32 rounding points, then
// evaluates transcendentals in double (closer to correctly-rounded than XLA f32).
// ----------------------------------------------------------------------------
__global__ void prep_kernel(const float* __restrict__ Lre,
                            const float* __restrict__ Lim,
                            const float* __restrict__ log_step)
{
    int p = threadIdx.x;
    float st = expf(log_step[p]);          // fp32 like jnp.exp
    float ar = Lre[p] * st;                // fp32 product like Lambda*step
    float ai = Lim[p] * st;

    double er = exp((double)ar);
    double lr = er * cos((double)ai);
    double li = er * sin((double)ai);
    g_lam[p] = make_float2((float)lr, (float)li);

    double Lr = (double)Lre[p], Li = (double)Lim[p];
    double den = Lr * Lr + Li * Li;
    double nr = lr - 1.0, ni = li;
    g_gamma[p] = make_float2((float)((nr * Lr + ni * Li) / den),
                             (float)((ni * Lr - nr * Li) / den));

    double erS = exp((double)ar * S_CHUNK);
    double aiS = (double)ai * S_CHUNK;
    g_lamS[p] = make_float2((float)(erS * cos(aiS)), (float)(erS * sin(aiS)));
}

// B_bar = gamma * B_tilde.  B layout (P, H, 2).  grid(P), block(H)
__global__ void make_bbar_kernel(const float* __restrict__ B)
{
    int p = blockIdx.x;
    int h = threadIdx.x;
    float2 g = g_gamma[p];
    float br = B[((size_t)p * H_DIM + h) * 2 + 0];
    float bi = B[((size_t)p * H_DIM + h) * 2 + 1];
    g_Bb[(size_t)p * H_DIM + h]             = g.x * br - g.y * bi;
    g_Bb[(size_t)(p + P_DIM) * H_DIM + h]   = g.x * bi + g.y * br;
}

// C2 rows: [2*Cr | -2*Ci].  C layout (H, P, 2).  grid(H), block(P)
__global__ void make_c2_kernel(const float* __restrict__ C)
{
    int h = blockIdx.x;
    int p = threadIdx.x;
    g_C2[(size_t)h * PP_DIM + p]          =  2.0f * C[((size_t)h * P_DIM + p) * 2 + 0];
    g_C2[(size_t)h * PP_DIM + P_DIM + p]  = -2.0f * C[((size_t)h * P_DIM + p) * 2 + 1];
}

// ----------------------------------------------------------------------------
// SGEMM: C[M,N] = A[M,K] @ B[N,K]^T  (both row-major, "TN" layout)
// 128x128 block tile, BK=16, 256 threads, 8x8 per thread.
// ----------------------------------------------------------------------------
#define BM 128
#define BN 128
#define BK 16
#define SSTR (BM + 4)   // 132: padded shared stride (16B-aligned, reduces conflicts)

template<int Kdim, int Ndim, bool EPI>
__device__ __forceinline__ void gemm_body(const float* __restrict__ A,
                                          const float* __restrict__ B,
                                          float* __restrict__ Cm,
                                          const float* __restrict__ D,
                                          const float* __restrict__ U)
{
    __shared__ __align__(16) float As[BK * SSTR];
    __shared__ __align__(16) float Bs[BK * SSTR];

    const int tid = threadIdx.x;
    const int m0 = blockIdx.y * BM;
    const int n0 = blockIdx.x * BN;

    const int lr = tid >> 2;          // 0..63 (row within tile, +64 on 2nd load)
    const int lk = (tid & 3) * 4;     // 0,4,8,12

    const float* Ag = A + (size_t)(m0 + lr) * Kdim + lk;
    const float* Bg = B + (size_t)(n0 + lr) * Kdim + lk;

    const int tx = tid & 15;          // col group
    const int ty = tid >> 4;          // row group

    float acc[8][8];
#pragma unroll
    for (int i = 0; i < 8; i++)
#pragma unroll
        for (int j = 0; j < 8; j++) acc[i][j] = 0.0f;

    for (int k0 = 0; k0 < Kdim; k0 += BK) {
#pragma unroll
        for (int i = 0; i < 2; i++) {
            float4 v = *(const float4*)(Ag + (size_t)(i * 64) * Kdim + k0);
            int r = lr + i * 64;
            As[(lk + 0) * SSTR + r] = v.x;
            As[(lk + 1) * SSTR + r] = v.y;
            As[(lk + 2) * SSTR + r] = v.z;
            As[(lk + 3) * SSTR + r] = v.w;
            float4 w = *(const float4*)(Bg + (size_t)(i * 64) * Kdim + k0);
            Bs[(lk + 0) * SSTR + r] = w.x;
            Bs[(lk + 1) * SSTR + r] = w.y;
            Bs[(lk + 2) * SSTR + r] = w.z;
            Bs[(lk + 3) * SSTR + r] = w.w;
        }
        __syncthreads();
#pragma unroll
        for (int k = 0; k < BK; k++) {
            float4 a0 = *(const float4*)&As[k * SSTR + ty * 8];
            float4 a1 = *(const float4*)&As[k * SSTR + ty * 8 + 4];
            float4 b0 = *(const float4*)&Bs[k * SSTR + tx * 8];
            float4 b1 = *(const float4*)&Bs[k * SSTR + tx * 8 + 4];
            float ar[8] = {a0.x, a0.y, a0.z, a0.w, a1.x, a1.y, a1.z, a1.w};
            float br[8] = {b0.x, b0.y, b0.z, b0.w, b1.x, b1.y, b1.z, b1.w};
#pragma unroll
            for (int i = 0; i < 8; i++)
#pragma unroll
                for (int j = 0; j < 8; j++)
                    acc[i][j] = fmaf(ar[i], br[j], acc[i][j]);
        }
        __syncthreads();
    }

    float dreg[8];
    if (EPI) {
#pragma unroll
        for (int j = 0; j < 8; j++) dreg[j] = __ldg(&D[n0 + tx * 8 + j]);
    }

#pragma unroll
    for (int i = 0; i < 8; i++) {
        int m = m0 + ty * 8 + i;
        float* Crow = Cm + (size_t)m * Ndim + n0 + tx * 8;
        if (EPI) {
            const float* Urow = U + (size_t)m * Ndim + n0 + tx * 8;
            float4 u0 = *(const float4*)(Urow);
            float4 u1 = *(const float4*)(Urow + 4);
            acc[i][0] = fmaf(dreg[0], u0.x, acc[i][0]);
            acc[i][1] = fmaf(dreg[1], u0.y, acc[i][1]);
            acc[i][2] = fmaf(dreg[2], u0.z, acc[i][2]);
            acc[i][3] = fmaf(dreg[3], u0.w, acc[i][3]);
            acc[i][4] = fmaf(dreg[4], u1.x, acc[i][4]);
            acc[i][5] = fmaf(dreg[5], u1.y, acc[i][5]);
            acc[i][6] = fmaf(dreg[6], u1.z, acc[i][6]);
            acc[i][7] = fmaf(dreg[7], u1.w, acc[i][7]);
        }
        *(float4*)(Crow)     = make_float4(acc[i][0], acc[i][1], acc[i][2], acc[i][3]);
        *(float4*)(Crow + 4) = make_float4(acc[i][4], acc[i][5], acc[i][6], acc[i][7]);
    }
}

__global__ void __launch_bounds__(256) gemm1_kernel(const float* __restrict__ u)
{
    gemm_body<H_DIM, PP_DIM, false>(u, g_Bb, g_X, nullptr, nullptr);
}

__global__ void __launch_bounds__(256) gemm2_kernel(float* __restrict__ out,
                                                    const float* __restrict__ D,
                                                    const float* __restrict__ u)
{
    gemm_body<PP_DIM, H_DIM, true>(g_X, g_C2, out, D, u);
}

// ----------------------------------------------------------------------------
// Chunked scan: x_t = lam * x_{t-1} + Bu_t   (in place on g_X)
// ----------------------------------------------------------------------------
__global__ void scan_local_kernel()
{
    int p = threadIdx.x;            // 0..255
    int c = blockIdx.x;             // chunk
    float2 lam = g_lam[p];
    float xr = 0.0f, xi = 0.0f;
    float* base = g_X + (size_t)c * S_CHUNK * PP_DIM;
#pragma unroll 4
    for (int t = 0; t < S_CHUNK; t++) {
        float br = base[t * PP_DIM + p];
        float bi = base[t * PP_DIM + P_DIM + p];
        float nr = fmaf(lam.x, xr, fmaf(-lam.y, xi, br));
        float ni = fmaf(lam.x, xi, fmaf( lam.y, xr, bi));
        xr = nr; xi = ni;
        base[t * PP_DIM + p] = xr;
        base[t * PP_DIM + P_DIM + p] = xi;
    }
    g_b[c][p] = make_float2(xr, xi);
}

__global__ void carry_scan_kernel()
{
    int p = threadIdx.x;
    float2 lS = g_lamS[p];
    float pr = 0.0f, pi = 0.0f;
    for (int c = 0; c < NCHUNK; c++) {
        g_pref[c][p] = make_float2(pr, pi);
        float2 b = g_b[c][p];
        float nr = fmaf(lS.x, pr, fmaf(-lS.y, pi, b.x));
        float ni = fmaf(lS.x, pi, fmaf( lS.y, pr, b.y));
        pr = nr; pi = ni;
    }
}

// x_global[t] = x_local[t] + lam^{t+1} * prefix_c   (chunks 1..NCHUNK-1)
__global__ void fixup_kernel()
{
    int p = threadIdx.x;
    int c = blockIdx.x + 1;
    float2 lam = g_lam[p];
    float2 pf = g_pref[c][p];
    float pwr = lam.x, pwi = lam.y;
    float* base = g_X + (size_t)c * S_CHUNK * PP_DIM;
#pragma unroll 4
    for (int t = 0; t < S_CHUNK; t++) {
        float cr = pwr * pf.x - pwi * pf.y;
        float ci = pwr * pf.y + pwi * pf.x;
        base[t * PP_DIM + p]         += cr;
        base[t * PP_DIM + P_DIM + p] += ci;
        float nr = pwr * lam.x - pwi * lam.y;
        float ni = pwr * lam.y + pwi * lam.x;
        pwr = nr; pwi = ni;
    }
}

// ----------------------------------------------------------------------------
// Launch
// ----------------------------------------------------------------------------
extern "C" void kernel_launch(void* const* d_in, const int* in_sizes, int n_in,
                              void* d_out, int out_size)
{
    const float* u   = (const float*)d_in[0];  // (L, H)
    const float* Lre = (const float*)d_in[1];  // (P,)
    const float* Lim = (const float*)d_in[2];  // (P,)
    const float* B   = (const float*)d_in[3];  // (P, H, 2)
    const float* C   = (const float*)d_in[4];  // (H, P, 2)
    const float* D   = (const float*)d_in[5];  // (H,)
    const float* ls  = (const float*)d_in[6];  // (P,)
    float* out = (float*)d_out;                // (L, H)

    prep_kernel<<<1, P_DIM>>>(Lre, Lim, ls);
    make_bbar_kernel<<<P_DIM, H_DIM>>>(B);
    make_c2_kernel<<<H_DIM, P_DIM>>>(C);

    // GEMM1: Bu = u @ Bb^T   -> g_X   (M=L, N=512, K=1024)
    gemm1_kernel<<<dim3(PP_DIM / BN, L_SEQ / BM), 256>>>(u);

    // Scan (in place on g_X)
    scan_local_kernel<<<NCHUNK, P_DIM>>>();
    carry_scan_kernel<<<1, P_DIM>>>();
    fixup_kernel<<<NCHUNK - 1, P_DIM>>>();

    // GEMM2: out = xs @ C2^T + D .* u   (M=L, N=1024, K=512)
    gemm2_kernel<<<dim3(H_DIM / BN, L_SEQ / BM), 256>>>(out, D, u);
}

// round 3
// speedup vs baseline: 2.3280x; 2.3280x over previous
#include <cuda_runtime.h>
#include <cstdint>

// Problem constants
#define L_SEQ  16384
#define H_DIM  1024
#define P_DIM  256
#define PP_DIM 512          // 2*P : [re | im] planes
#define NCHUNK 128
#define S_CHUNK 128         // L = NCHUNK * S_CHUNK

// ----------------------------------------------------------------------------
// Device scratch (static globals; no cudaMalloc allowed)
// ----------------------------------------------------------------------------
__device__ float  g_X[(size_t)L_SEQ * PP_DIM];   // Bu -> xs, in place (33.5 MB)
__device__ float  g_Bb[PP_DIM * H_DIM];          // [Bb_re | Bb_im] x H  (row-major PPxH)
__device__ float  g_C2[H_DIM * PP_DIM];          // rows h: [2*Cr | -2*Ci]
__device__ float2 g_lam[P_DIM];
__device__ float2 g_gamma[P_DIM];
__device__ float2 g_lamS[P_DIM];
__device__ float2 g_b[NCHUNK][P_DIM];
__device__ float2 g_pref[NCHUNK][P_DIM];

// ----------------------------------------------------------------------------
// prep: Lambda_bar, gamma, lam^S (fp32 rounding points match jax; transcendentals
// in double)
// ----------------------------------------------------------------------------
__global__ void prep_kernel(const float* __restrict__ Lre,
                            const float* __restrict__ Lim,
                            const float* __restrict__ log_step)
{
    int p = threadIdx.x;
    float st = expf(log_step[p]);
    float ar = Lre[p] * st;
    float ai = Lim[p] * st;

    double er = exp((double)ar);
    double lr = er * cos((double)ai);
    double li = er * sin((double)ai);
    g_lam[p] = make_float2((float)lr, (float)li);

    double Lr = (double)Lre[p], Li = (double)Lim[p];
    double den = Lr * Lr + Li * Li;
    double nr = lr - 1.0, ni = li;
    g_gamma[p] = make_float2((float)((nr * Lr + ni * Li) / den),
                             (float)((ni * Lr - nr * Li) / den));

    double erS = exp((double)ar * S_CHUNK);
    double aiS = (double)ai * S_CHUNK;
    g_lamS[p] = make_float2((float)(erS * cos(aiS)), (float)(erS * sin(aiS)));
}

__global__ void make_bbar_kernel(const float* __restrict__ B)
{
    int p = blockIdx.x;
    int h = threadIdx.x;
    float2 g = g_gamma[p];
    float br = B[((size_t)p * H_DIM + h) * 2 + 0];
    float bi = B[((size_t)p * H_DIM + h) * 2 + 1];
    g_Bb[(size_t)p * H_DIM + h]           = g.x * br - g.y * bi;
    g_Bb[(size_t)(p + P_DIM) * H_DIM + h] = g.x * bi + g.y * br;
}

__global__ void make_c2_kernel(const float* __restrict__ C)
{
    int h = blockIdx.x;
    int p = threadIdx.x;
    g_C2[(size_t)h * PP_DIM + p]         =  2.0f * C[((size_t)h * P_DIM + p) * 2 + 0];
    g_C2[(size_t)h * PP_DIM + P_DIM + p] = -2.0f * C[((size_t)h * P_DIM + p) * 2 + 1];
}

// ----------------------------------------------------------------------------
// TF32 tensor-core GEMM:  C[M,N] = A[M,K] @ B[N,K]^T   (both row-major)
// 128x128 tile, BK=16, 2-stage cp.async pipeline, ldmatrix + mma.sync tf32.
// ----------------------------------------------------------------------------
#define BM 128
#define BN 128
#define BK 16
#define SROW 20   // padded floats per smem row (16 + 4) -> conflict-free ldmatrix

__device__ __forceinline__ uint32_t s2u(const void* p) {
    return (uint32_t)__cvta_generic_to_shared(p);
}
__device__ __forceinline__ void cp16(uint32_t dst, const void* src) {
    asm volatile("cp.async.cg.shared.global [%0], [%1], 16;\n" :: "r"(dst), "l"(src));
}
__device__ __forceinline__ void cp_commit() { asm volatile("cp.async.commit_group;\n"); }
__device__ __forceinline__ void cp_wait1()  { asm volatile("cp.async.wait_group 1;\n"); }
__device__ __forceinline__ void ldsm4(uint32_t& r0, uint32_t& r1, uint32_t& r2, uint32_t& r3,
                                      uint32_t addr) {
    asm volatile("ldmatrix.sync.aligned.m8n8.x4.shared.b16 {%0,%1,%2,%3}, [%4];\n"
                 : "=r"(r0), "=r"(r1), "=r"(r2), "=r"(r3) : "r"(addr));
}
__device__ __forceinline__ uint32_t f2tf(uint32_t x) {
    uint32_t y;
    asm("cvt.rna.tf32.f32 %0, %1;\n" : "=r"(y) : "f"(__uint_as_float(x)));
    return y;
}
__device__ __forceinline__ void mma_tf32(float c[4], const uint32_t a[4], const uint32_t b[2]) {
    asm volatile(
        "mma.sync.aligned.m16n8k8.row.col.f32.tf32.tf32.f32 "
        "{%0,%1,%2,%3}, {%4,%5,%6,%7}, {%8,%9}, {%0,%1,%2,%3};\n"
        : "+f"(c[0]), "+f"(c[1]), "+f"(c[2]), "+f"(c[3])
        : "r"(a[0]), "r"(a[1]), "r"(a[2]), "r"(a[3]), "r"(b[0]), "r"(b[1]));
}

template<int Kdim, int Ndim, bool EPI>
__device__ __forceinline__ void gemm_tc(const float* __restrict__ A,
                                        const float* __restrict__ B,
                                        float* __restrict__ Cm,
                                        const float* __restrict__ D,
                                        const float* __restrict__ U)
{
    __shared__ __align__(16) float sA[2][BM * SROW];
    __shared__ __align__(16) float sB[2][BN * SROW];

    const int tid  = threadIdx.x;
    const int lane = tid & 31;
    const int warp = tid >> 5;       // 8 warps: 2(m) x 4(n)
    const int wm   = warp >> 2;      // 0..1  -> 64 rows each
    const int wn   = warp & 3;       // 0..3  -> 32 cols each
    const int m0   = blockIdx.y * BM;
    const int n0   = blockIdx.x * BN;

    // cp.async tile loader: 128 rows x 4 chunks of 16B; 256 thr x 2
    const int lr0 = tid >> 2;           // row for i=0 (0..63)
    const int lc  = (tid & 3) * 4;      // float col 0,4,8,12

    auto load_stage = [&](int buf, int k0) {
#pragma unroll
        for (int i = 0; i < 2; i++) {
            int r = lr0 + i * 64;
            cp16(s2u(&sA[buf][r * SROW + lc]), A + (size_t)(m0 + r) * Kdim + k0 + lc);
            cp16(s2u(&sB[buf][r * SROW + lc]), B + (size_t)(n0 + r) * Kdim + k0 + lc);
        }
    };

    // ldmatrix lane addressing: row = lane&15 within 16-row tile, chunk-sel = lane>>4
    const int ldrow = lane & 15;
    const int ldsel = lane >> 4;

    float acc[4][4][4];
#pragma unroll
    for (int i = 0; i < 4; i++)
#pragma unroll
        for (int j = 0; j < 4; j++)
#pragma unroll
            for (int v = 0; v < 4; v++) acc[i][j][v] = 0.0f;

    const int Ktiles = Kdim / BK;
    load_stage(0, 0);            cp_commit();
    load_stage(1, BK);           cp_commit();

    for (int kt = 0; kt < Ktiles; kt++) {
        cp_wait1();
        __syncthreads();
        const int buf = kt & 1;

#pragma unroll
        for (int ks = 0; ks < 2; ks++) {
            uint32_t af[4][4];
#pragma unroll
            for (int mt = 0; mt < 4; mt++) {
                uint32_t addr = s2u(&sA[buf][(wm * 64 + mt * 16 + ldrow) * SROW
                                             + (ks * 2 + ldsel) * 4]);
                ldsm4(af[mt][0], af[mt][1], af[mt][2], af[mt][3], addr);
#pragma unroll
                for (int v = 0; v < 4; v++) af[mt][v] = f2tf(af[mt][v]);
            }
            uint32_t bf[4][2];
#pragma unroll
            for (int pair = 0; pair < 2; pair++) {
                uint32_t q0, q1, q2, q3;
                uint32_t addr = s2u(&sB[buf][(wn * 32 + pair * 16 + ldrow) * SROW
                                             + (ks * 2 + ldsel) * 4]);
                ldsm4(q0, q1, q2, q3, addr);
                bf[pair * 2 + 0][0] = f2tf(q0);
                bf[pair * 2 + 0][1] = f2tf(q2);
                bf[pair * 2 + 1][0] = f2tf(q1);
                bf[pair * 2 + 1][1] = f2tf(q3);
            }
#pragma unroll
            for (int mt = 0; mt < 4; mt++)
#pragma unroll
                for (int nt = 0; nt < 4; nt++)
                    mma_tf32(acc[mt][nt], af[mt], bf[nt]);
        }

        __syncthreads();
        if (kt + 2 < Ktiles) load_stage(buf, (kt + 2) * BK);
        cp_commit();
    }

    // Epilogue: c0:(gid, 2*tig) c1:(gid, 2*tig+1) c2:(gid+8, ..) c3
    const int gid = lane >> 2;
    const int tig = lane & 3;
#pragma unroll
    for (int mt = 0; mt < 4; mt++) {
        int r0 = m0 + wm * 64 + mt * 16 + gid;
        int r1 = r0 + 8;
#pragma unroll
        for (int nt = 0; nt < 4; nt++) {
            int col = n0 + wn * 32 + nt * 8 + tig * 2;
            float c0 = acc[mt][nt][0], c1 = acc[mt][nt][1];
            float c2 = acc[mt][nt][2], c3 = acc[mt][nt][3];
            if (EPI) {
                float d0 = __ldg(&D[col]), d1 = __ldg(&D[col + 1]);
                float2 u0 = *(const float2*)&U[(size_t)r0 * Ndim + col];
                float2 u1 = *(const float2*)&U[(size_t)r1 * Ndim + col];
                c0 = fmaf(d0, u0.x, c0);  c1 = fmaf(d1, u0.y, c1);
                c2 = fmaf(d0, u1.x, c2);  c3 = fmaf(d1, u1.y, c3);
            }
            *(float2*)&Cm[(size_t)r0 * Ndim + col] = make_float2(c0, c1);
            *(float2*)&Cm[(size_t)r1 * Ndim + col] = make_float2(c2, c3);
        }
    }
}

__global__ void __launch_bounds__(256) gemm1_kernel(const float* __restrict__ u)
{
    gemm_tc<H_DIM, PP_DIM, false>(u, g_Bb, g_X, nullptr, nullptr);
}

__global__ void __launch_bounds__(256) gemm2_kernel(float* __restrict__ out,
                                                    const float* __restrict__ D,
                                                    const float* __restrict__ u)
{
    gemm_tc<PP_DIM, H_DIM, true>(g_X, g_C2, out, D, u);
}

// ----------------------------------------------------------------------------
// Chunked scan: x_t = lam * x_{t-1} + Bu_t   (in place on g_X)
// ----------------------------------------------------------------------------
__global__ void scan_local_kernel()
{
    int p = threadIdx.x;
    int c = blockIdx.x;
    float2 lam = g_lam[p];
    float xr = 0.0f, xi = 0.0f;
    float* base = g_X + (size_t)c * S_CHUNK * PP_DIM;
#pragma unroll 4
    for (int t = 0; t < S_CHUNK; t++) {
        float br = base[t * PP_DIM + p];
        float bi = base[t * PP_DIM + P_DIM + p];
        float nr = fmaf(lam.x, xr, fmaf(-lam.y, xi, br));
        float ni = fmaf(lam.x, xi, fmaf( lam.y, xr, bi));
        xr = nr; xi = ni;
        base[t * PP_DIM + p] = xr;
        base[t * PP_DIM + P_DIM + p] = xi;
    }
    g_b[c][p] = make_float2(xr, xi);
}

__global__ void carry_scan_kernel()
{
    int p = threadIdx.x;
    float2 lS = g_lamS[p];
    float pr = 0.0f, pi = 0.0f;
    for (int c = 0; c < NCHUNK; c++) {
        g_pref[c][p] = make_float2(pr, pi);
        float2 b = g_b[c][p];
        float nr = fmaf(lS.x, pr, fmaf(-lS.y, pi, b.x));
        float ni = fmaf(lS.x, pi, fmaf( lS.y, pr, b.y));
        pr = nr; pi = ni;
    }
}

__global__ void fixup_kernel()
{
    int p = threadIdx.x;
    int c = blockIdx.x + 1;
    float2 lam = g_lam[p];
    float2 pf = g_pref[c][p];
    float pwr = lam.x, pwi = lam.y;
    float* base = g_X + (size_t)c * S_CHUNK * PP_DIM;
#pragma unroll 4
    for (int t = 0; t < S_CHUNK; t++) {
        float cr = pwr * pf.x - pwi * pf.y;
        float ci = pwr * pf.y + pwi * pf.x;
        base[t * PP_DIM + p]         += cr;
        base[t * PP_DIM + P_DIM + p] += ci;
        float nr = pwr * lam.x - pwi * lam.y;
        float ni = pwr * lam.y + pwi * lam.x;
        pwr = nr; pwi = ni;
    }
}

// ----------------------------------------------------------------------------
// Launch
// ----------------------------------------------------------------------------
extern "C" void kernel_launch(void* const* d_in, const int* in_sizes, int n_in,
                              void* d_out, int out_size)
{
    const float* u   = (const float*)d_in[0];  // (L, H)
    const float* Lre = (const float*)d_in[1];  // (P,)
    const float* Lim = (const float*)d_in[2];  // (P,)
    const float* B   = (const float*)d_in[3];  // (P, H, 2)
    const float* C   = (const float*)d_in[4];  // (H, P, 2)
    const float* D   = (const float*)d_in[5];  // (H,)
    const float* ls  = (const float*)d_in[6];  // (P,)
    float* out = (float*)d_out;                // (L, H)

    prep_kernel<<<1, P_DIM>>>(Lre, Lim, ls);
    make_bbar_kernel<<<P_DIM, H_DIM>>>(B);
    make_c2_kernel<<<H_DIM, P_DIM>>>(C);

    // GEMM1: Bu = u @ Bb^T   -> g_X   (M=L, N=512, K=1024)
    gemm1_kernel<<<dim3(PP_DIM / BN, L_SEQ / BM), 256>>>(u);

    // Scan (in place on g_X)
    scan_local_kernel<<<NCHUNK, P_DIM>>>();
    carry_scan_kernel<<<1, P_DIM>>>();
    fixup_kernel<<<NCHUNK - 1, P_DIM>>>();

    // GEMM2: out = xs @ C2^T + D .* u   (M=L, N=1024, K=512)
    gemm2_kernel<<<dim3(H_DIM / BN, L_SEQ / BM), 256>>>(out, D, u);
}

// round 6
// speedup vs baseline: 3.1285x; 1.3439x over previous
#include <cuda_runtime.h>
#include <cuda_bf16.h>
#include <cstdint>

// Problem constants
#define L_SEQ  16384
#define H_DIM  1024
#define P_DIM  256
#define PP_DIM 512          // 2*P : [re | im] planes
#define NCHUNK 256
#define S_CHUNK 64          // L = NCHUNK * S_CHUNK

// ----------------------------------------------------------------------------
// Device scratch (static globals; no cudaMalloc allowed)
// ----------------------------------------------------------------------------
__device__ float          g_X [(size_t)L_SEQ * PP_DIM];   // Bu (fp32 scan workspace)
__device__ __nv_bfloat16  g_Xh[(size_t)L_SEQ * PP_DIM];   // xs rounded to bf16 (gemm2 A)
__device__ __nv_bfloat16  g_U [(size_t)L_SEQ * H_DIM];    // u rounded to bf16 (gemm1 A)
__device__ __nv_bfloat16  g_Bbh[PP_DIM * H_DIM];          // B_bar bf16 [re|im] x H
__device__ __nv_bfloat16  g_C2h[H_DIM * PP_DIM];          // [2*Cr | -2*Ci] bf16
__device__ float2 g_lam[P_DIM];
__device__ float2 g_gamma[P_DIM];
__device__ float2 g_lamS[P_DIM];
__device__ float2 g_b[NCHUNK][P_DIM];
__device__ float2 g_pref[NCHUNK][P_DIM];

// ----------------------------------------------------------------------------
// prep: Lambda_bar, gamma, lam^S (fp32 rounding points match jax; transcendentals
// in double)
// ----------------------------------------------------------------------------
__global__ void prep_kernel(const float* __restrict__ Lre,
                            const float* __restrict__ Lim,
                            const float* __restrict__ log_step)
{
    int p = threadIdx.x;
    float st = expf(log_step[p]);
    float ar = Lre[p] * st;
    float ai = Lim[p] * st;

    double er = exp((double)ar);
    double lr = er * cos((double)ai);
    double li = er * sin((double)ai);
    g_lam[p] = make_float2((float)lr, (float)li);

    double Lr = (double)Lre[p], Li = (double)Lim[p];
    double den = Lr * Lr + Li * Li;
    double nr = lr - 1.0, ni = li;
    g_gamma[p] = make_float2((float)((nr * Lr + ni * Li) / den),
                             (float)((ni * Lr - nr * Li) / den));

    double erS = exp((double)ar * S_CHUNK);
    double aiS = (double)ai * S_CHUNK;
    g_lamS[p] = make_float2((float)(erS * cos(aiS)), (float)(erS * sin(aiS)));
}

__global__ void make_bbar_kernel(const float* __restrict__ B)
{
    int p = blockIdx.x;
    int h = threadIdx.x;
    float2 g = g_gamma[p];
    float br = B[((size_t)p * H_DIM + h) * 2 + 0];
    float bi = B[((size_t)p * H_DIM + h) * 2 + 1];
    g_Bbh[(size_t)p * H_DIM + h]           = __float2bfloat16_rn(g.x * br - g.y * bi);
    g_Bbh[(size_t)(p + P_DIM) * H_DIM + h] = __float2bfloat16_rn(g.x * bi + g.y * br);
}

__global__ void make_c2_kernel(const float* __restrict__ C)
{
    int h = blockIdx.x;
    int p = threadIdx.x;
    g_C2h[(size_t)h * PP_DIM + p]         = __float2bfloat16_rn( 2.0f * C[((size_t)h * P_DIM + p) * 2 + 0]);
    g_C2h[(size_t)h * PP_DIM + P_DIM + p] = __float2bfloat16_rn(-2.0f * C[((size_t)h * P_DIM + p) * 2 + 1]);
}

// u (fp32) -> g_U (bf16, round-to-nearest).  8 elems / thread.
__global__ void round_u_kernel(const float* __restrict__ u)
{
    size_t i = ((size_t)blockIdx.x * blockDim.x + threadIdx.x) * 8;
    float4 a = *(const float4*)(u + i);
    float4 b = *(const float4*)(u + i + 4);
    __nv_bfloat162 h0 = __floats2bfloat162_rn(a.x, a.y);
    __nv_bfloat162 h1 = __floats2bfloat162_rn(a.z, a.w);
    __nv_bfloat162 h2 = __floats2bfloat162_rn(b.x, b.y);
    __nv_bfloat162 h3 = __floats2bfloat162_rn(b.z, b.w);
    uint4 out;
    out.x = *(uint32_t*)&h0;  out.y = *(uint32_t*)&h1;
    out.z = *(uint32_t*)&h2;  out.w = *(uint32_t*)&h3;
    *(uint4*)(g_U + i) = out;
}

// ----------------------------------------------------------------------------
// BF16 tensor-core GEMM:  C[M,N] = A[M,K] @ B[N,K]^T   (row-major, bf16 in, fp32 out)
// 128x128 tile, BK=32, 2-stage cp.async pipeline (static smem, <48KB),
// ldmatrix + mma.sync.m16n8k16.bf16.
// ----------------------------------------------------------------------------
#define BM 128
#define BN 128
#define BK 32
#define SROWB 40          // padded bf16 elems per smem row (64B + 16B pad)

__device__ __forceinline__ uint32_t s2u(const void* p) {
    return (uint32_t)__cvta_generic_to_shared(p);
}
__device__ __forceinline__ void cp16(uint32_t dst, const void* src) {
    asm volatile("cp.async.cg.shared.global [%0], [%1], 16;\n" :: "r"(dst), "l"(src));
}
__device__ __forceinline__ void cp_commit() { asm volatile("cp.async.commit_group;\n"); }
__device__ __forceinline__ void cp_wait1()  { asm volatile("cp.async.wait_group 1;\n"); }
__device__ __forceinline__ void ldsm4(uint32_t& r0, uint32_t& r1, uint32_t& r2, uint32_t& r3,
                                      uint32_t addr) {
    asm volatile("ldmatrix.sync.aligned.m8n8.x4.shared.b16 {%0,%1,%2,%3}, [%4];\n"
                 : "=r"(r0), "=r"(r1), "=r"(r2), "=r"(r3) : "r"(addr));
}
__device__ __forceinline__ void mma_bf16(float c[4], const uint32_t a[4], const uint32_t b[2]) {
    asm volatile(
        "mma.sync.aligned.m16n8k16.row.col.f32.bf16.bf16.f32 "
        "{%0,%1,%2,%3}, {%4,%5,%6,%7}, {%8,%9}, {%0,%1,%2,%3};\n"
        : "+f"(c[0]), "+f"(c[1]), "+f"(c[2]), "+f"(c[3])
        : "r"(a[0]), "r"(a[1]), "r"(a[2]), "r"(a[3]), "r"(b[0]), "r"(b[1]));
}

template<int Kdim, int Ndim, bool EPI>
__device__ __forceinline__ void gemm_tc(const __nv_bfloat16* __restrict__ A,
                                        const __nv_bfloat16* __restrict__ B,
                                        float* __restrict__ Cm,
                                        const float* __restrict__ D,
                                        const float* __restrict__ U)
{
    __shared__ __align__(16) __nv_bfloat16 sA[2][BM * SROWB];
    __shared__ __align__(16) __nv_bfloat16 sB[2][BN * SROWB];

    const int tid  = threadIdx.x;
    const int lane = tid & 31;
    const int warp = tid >> 5;       // 8 warps: 2(m) x 4(n)
    const int wm   = warp >> 2;      // 0..1  -> 64 rows
    const int wn   = warp & 3;       // 0..3  -> 32 cols
    const int m0   = blockIdx.y * BM;
    const int n0   = blockIdx.x * BN;

    // loader: 128 rows x 4 chunks(16B = 8 bf16); 256 thr -> 2 rows / thread
    const int lr0 = tid >> 2;            // 0..63
    const int lc  = (tid & 3) * 8;       // bf16 col 0,8,16,24

    auto load_stage = [&](int s, int k0) {
#pragma unroll
        for (int i = 0; i < 2; i++) {
            int r = lr0 + i * 64;
            cp16(s2u(&sA[s][r * SROWB + lc]), A + (size_t)(m0 + r) * Kdim + k0 + lc);
            cp16(s2u(&sB[s][r * SROWB + lc]), B + (size_t)(n0 + r) * Kdim + k0 + lc);
        }
    };

    const int ldrow = lane & 15;
    const int ldsel = lane >> 4;

    float acc[4][4][4];
#pragma unroll
    for (int i = 0; i < 4; i++)
#pragma unroll
        for (int j = 0; j < 4; j++)
#pragma unroll
            for (int v = 0; v < 4; v++) acc[i][j][v] = 0.0f;

    const int Ktiles = Kdim / BK;       // 32 (gemm1) / 16 (gemm2)
    load_stage(0, 0);       cp_commit();
    load_stage(1, BK);      cp_commit();

    for (int kt = 0; kt < Ktiles; kt++) {
        cp_wait1();
        __syncthreads();
        const int buf = kt & 1;

#pragma unroll
        for (int ks = 0; ks < 2; ks++) {
            uint32_t af[4][4];
#pragma unroll
            for (int mt = 0; mt < 4; mt++) {
                uint32_t addr = s2u(&sA[buf][(wm * 64 + mt * 16 + ldrow) * SROWB
                                            + ks * 16 + ldsel * 8]);
                ldsm4(af[mt][0], af[mt][1], af[mt][2], af[mt][3], addr);
            }
            uint32_t bfr[4][2];
#pragma unroll
            for (int pair = 0; pair < 2; pair++) {
                uint32_t q0, q1, q2, q3;
                uint32_t addr = s2u(&sB[buf][(wn * 32 + pair * 16 + ldrow) * SROWB
                                            + ks * 16 + ldsel * 8]);
                ldsm4(q0, q1, q2, q3, addr);
                bfr[pair * 2 + 0][0] = q0;  bfr[pair * 2 + 0][1] = q2;
                bfr[pair * 2 + 1][0] = q1;  bfr[pair * 2 + 1][1] = q3;
            }
#pragma unroll
            for (int mt = 0; mt < 4; mt++)
#pragma unroll
                for (int nt = 0; nt < 4; nt++)
                    mma_bf16(acc[mt][nt], af[mt], bfr[nt]);
        }

        __syncthreads();
        if (kt + 2 < Ktiles) load_stage(buf, (kt + 2) * BK);
        cp_commit();
    }

    // Epilogue: per lane c0:(gid,2t) c1:(gid,2t+1) c2:(gid+8,2t) c3:(gid+8,2t+1)
    const int gid = lane >> 2;
    const int tig = lane & 3;
#pragma unroll
    for (int mt = 0; mt < 4; mt++) {
        int r0 = m0 + wm * 64 + mt * 16 + gid;
        int r1 = r0 + 8;
#pragma unroll
        for (int nt = 0; nt < 4; nt++) {
            int col = n0 + wn * 32 + nt * 8 + tig * 2;
            float c0 = acc[mt][nt][0], c1 = acc[mt][nt][1];
            float c2 = acc[mt][nt][2], c3 = acc[mt][nt][3];
            if (EPI) {
                float d0 = __ldg(&D[col]), d1 = __ldg(&D[col + 1]);
                float2 u0 = *(const float2*)&U[(size_t)r0 * Ndim + col];
                float2 u1 = *(const float2*)&U[(size_t)r1 * Ndim + col];
                c0 = fmaf(d0, u0.x, c0);  c1 = fmaf(d1, u0.y, c1);
                c2 = fmaf(d0, u1.x, c2);  c3 = fmaf(d1, u1.y, c3);
            }
            *(float2*)&Cm[(size_t)r0 * Ndim + col] = make_float2(c0, c1);
            *(float2*)&Cm[(size_t)r1 * Ndim + col] = make_float2(c2, c3);
        }
    }
}

__global__ void __launch_bounds__(256) gemm1_kernel()
{
    gemm_tc<H_DIM, PP_DIM, false>(g_U, g_Bbh, g_X, nullptr, nullptr);
}

__global__ void __launch_bounds__(256) gemm2_kernel(float* __restrict__ out,
                                                    const float* __restrict__ D,
                                                    const float* __restrict__ u)
{
    gemm_tc<PP_DIM, H_DIM, true>(g_Xh, g_C2h, out, D, u);
}

// ----------------------------------------------------------------------------
// Chunked scan: x_t = lam * x_{t-1} + Bu_t
// ----------------------------------------------------------------------------
__global__ void scan_local_kernel()
{
    int p = threadIdx.x;
    int c = blockIdx.x;
    float2 lam = g_lam[p];
    float xr = 0.0f, xi = 0.0f;
    float* base = g_X + (size_t)c * S_CHUNK * PP_DIM;
    if (c == 0) {
        __nv_bfloat16* hb = g_Xh;
#pragma unroll 4
        for (int t = 0; t < S_CHUNK; t++) {
            float br = base[t * PP_DIM + p];
            float bi = base[t * PP_DIM + P_DIM + p];
            float nr = fmaf(lam.x, xr, fmaf(-lam.y, xi, br));
            float ni = fmaf(lam.x, xi, fmaf( lam.y, xr, bi));
            xr = nr; xi = ni;
            hb[t * PP_DIM + p]         = __float2bfloat16_rn(xr);
            hb[t * PP_DIM + P_DIM + p] = __float2bfloat16_rn(xi);
        }
    } else {
#pragma unroll 4
        for (int t = 0; t < S_CHUNK; t++) {
            float br = base[t * PP_DIM + p];
            float bi = base[t * PP_DIM + P_DIM + p];
            float nr = fmaf(lam.x, xr, fmaf(-lam.y, xi, br));
            float ni = fmaf(lam.x, xi, fmaf( lam.y, xr, bi));
            xr = nr; xi = ni;
            base[t * PP_DIM + p]         = xr;
            base[t * PP_DIM + P_DIM + p] = xi;
        }
    }
    g_b[c][p] = make_float2(xr, xi);
}

__global__ void carry_scan_kernel()
{
    int p = threadIdx.x;
    float2 lS = g_lamS[p];
    float pr = 0.0f, pi = 0.0f;
    for (int c = 0; c < NCHUNK; c++) {
        g_pref[c][p] = make_float2(pr, pi);
        float2 b = g_b[c][p];
        float nr = fmaf(lS.x, pr, fmaf(-lS.y, pi, b.x));
        float ni = fmaf(lS.x, pi, fmaf( lS.y, pr, b.y));
        pr = nr; pi = ni;
    }
}

// x_global[t] = x_local[t] + lam^{t+1} * prefix_c ; write bf16 only
__global__ void fixup_kernel()
{
    int p = threadIdx.x;
    int c = blockIdx.x + 1;
    float2 lam = g_lam[p];
    float2 pf = g_pref[c][p];
    float pwr = lam.x, pwi = lam.y;
    const float* base = g_X + (size_t)c * S_CHUNK * PP_DIM;
    __nv_bfloat16* hb = g_Xh + (size_t)c * S_CHUNK * PP_DIM;
#pragma unroll 4
    for (int t = 0; t < S_CHUNK; t++) {
        float cr = pwr * pf.x - pwi * pf.y;
        float ci = pwr * pf.y + pwi * pf.x;
        hb[t * PP_DIM + p]         = __float2bfloat16_rn(base[t * PP_DIM + p] + cr);
        hb[t * PP_DIM + P_DIM + p] = __float2bfloat16_rn(base[t * PP_DIM + P_DIM + p] + ci);
        float nr = pwr * lam.x - pwi * lam.y;
        float ni = pwr * lam.y + pwi * lam.x;
        pwr = nr; pwi = ni;
    }
}

// ----------------------------------------------------------------------------
// Launch
// ----------------------------------------------------------------------------
extern "C" void kernel_launch(void* const* d_in, const int* in_sizes, int n_in,
                              void* d_out, int out_size)
{
    const float* u   = (const float*)d_in[0];  // (L, H)
    const float* Lre = (const float*)d_in[1];  // (P,)
    const float* Lim = (const float*)d_in[2];  // (P,)
    const float* B   = (const float*)d_in[3];  // (P, H, 2)
    const float* C   = (const float*)d_in[4];  // (H, P, 2)
    const float* D   = (const float*)d_in[5];  // (H,)
    const float* ls  = (const float*)d_in[6];  // (P,)
    float* out = (float*)d_out;                // (L, H)

    prep_kernel<<<1, P_DIM>>>(Lre, Lim, ls);
    make_bbar_kernel<<<P_DIM, H_DIM>>>(B);
    make_c2_kernel<<<H_DIM, P_DIM>>>(C);
    round_u_kernel<<<(L_SEQ * H_DIM / 8) / 256, 256>>>(u);

    // GEMM1: Bu = u @ Bb^T   -> g_X   (M=L, N=512, K=1024)
    gemm1_kernel<<<dim3(PP_DIM / BN, L_SEQ / BM), 256>>>();

    // Scan: g_X (fp32) -> g_Xh (bf16)
    scan_local_kernel<<<NCHUNK, P_DIM>>>();
    carry_scan_kernel<<<1, P_DIM>>>();
    fixup_kernel<<<NCHUNK - 1, P_DIM>>>();

    // GEMM2: out = xs @ C2^T + D .* u   (M=L, N=1024, K=512)
    gemm2_kernel<<<dim3(H_DIM / BN, L_SEQ / BM), 256>>>(out, D, u);
}

// round 9
// speedup vs baseline: 3.9915x; 1.2759x over previous
#include <cuda_runtime.h>
#include <cuda_bf16.h>
#include <cstdint>

// Problem constants
#define L_SEQ  16384
#define H_DIM  1024
#define P_DIM  256
#define PP_DIM 512          // 2*P : [re | im] planes
#define NCHUNK 256
#define S_CHUNK 64          // L = NCHUNK * S_CHUNK

// ----------------------------------------------------------------------------
// Device scratch (static globals; no cudaMalloc allowed)
// ----------------------------------------------------------------------------
__device__ float          g_X [(size_t)L_SEQ * PP_DIM];   // Bu (fp32 scan workspace)
__device__ __nv_bfloat16  g_Xh[(size_t)L_SEQ * PP_DIM];   // xs rounded to bf16 (gemm2 A)
__device__ __nv_bfloat16  g_U [(size_t)L_SEQ * H_DIM];    // u rounded to bf16 (gemm1 A)
__device__ __nv_bfloat16  g_Bbh[PP_DIM * H_DIM];          // B_bar bf16 [re|im] x H
__device__ __nv_bfloat16  g_C2h[H_DIM * PP_DIM];          // [2*Cr | -2*Ci] bf16
__device__ float2 g_lam[P_DIM];
__device__ float2 g_gamma[P_DIM];
__device__ float2 g_lamS[P_DIM];
__device__ float2 g_b[NCHUNK][P_DIM];
__device__ float2 g_pref[NCHUNK][P_DIM];

// ----------------------------------------------------------------------------
// prep: Lambda_bar, gamma, lam^S (fp32 rounding points match jax; transcendentals
// in double)
// ----------------------------------------------------------------------------
__global__ void prep_kernel(const float* __restrict__ Lre,
                            const float* __restrict__ Lim,
                            const float* __restrict__ log_step)
{
    int p = threadIdx.x;
    float st = expf(log_step[p]);
    float ar = Lre[p] * st;
    float ai = Lim[p] * st;

    double er = exp((double)ar);
    double lr = er * cos((double)ai);
    double li = er * sin((double)ai);
    g_lam[p] = make_float2((float)lr, (float)li);

    double Lr = (double)Lre[p], Li = (double)Lim[p];
    double den = Lr * Lr + Li * Li;
    double nr = lr - 1.0, ni = li;
    g_gamma[p] = make_float2((float)((nr * Lr + ni * Li) / den),
                             (float)((ni * Lr - nr * Li) / den));

    double erS = exp((double)ar * S_CHUNK);
    double aiS = (double)ai * S_CHUNK;
    g_lamS[p] = make_float2((float)(erS * cos(aiS)), (float)(erS * sin(aiS)));
}

__global__ void make_bbar_kernel(const float* __restrict__ B)
{
    int p = blockIdx.x;
    int h = threadIdx.x;
    float2 g = g_gamma[p];
    float br = B[((size_t)p * H_DIM + h) * 2 + 0];
    float bi = B[((size_t)p * H_DIM + h) * 2 + 1];
    g_Bbh[(size_t)p * H_DIM + h]           = __float2bfloat16_rn(g.x * br - g.y * bi);
    g_Bbh[(size_t)(p + P_DIM) * H_DIM + h] = __float2bfloat16_rn(g.x * bi + g.y * br);
}

__global__ void make_c2_kernel(const float* __restrict__ C)
{
    int h = blockIdx.x;
    int p = threadIdx.x;
    g_C2h[(size_t)h * PP_DIM + p]         = __float2bfloat16_rn( 2.0f * C[((size_t)h * P_DIM + p) * 2 + 0]);
    g_C2h[(size_t)h * PP_DIM + P_DIM + p] = __float2bfloat16_rn(-2.0f * C[((size_t)h * P_DIM + p) * 2 + 1]);
}

// u (fp32) -> g_U (bf16, round-to-nearest).  8 elems / thread.
__global__ void round_u_kernel(const float* __restrict__ u)
{
    size_t i = ((size_t)blockIdx.x * blockDim.x + threadIdx.x) * 8;
    float4 a = *(const float4*)(u + i);
    float4 b = *(const float4*)(u + i + 4);
    __nv_bfloat162 h0 = __floats2bfloat162_rn(a.x, a.y);
    __nv_bfloat162 h1 = __floats2bfloat162_rn(a.z, a.w);
    __nv_bfloat162 h2 = __floats2bfloat162_rn(b.x, b.y);
    __nv_bfloat162 h3 = __floats2bfloat162_rn(b.z, b.w);
    uint4 out;
    out.x = *(uint32_t*)&h0;  out.y = *(uint32_t*)&h1;
    out.z = *(uint32_t*)&h2;  out.w = *(uint32_t*)&h3;
    *(uint4*)(g_U + i) = out;
}

// ----------------------------------------------------------------------------
// BF16 tensor-core GEMM:  C[M,N] = A[M,K] @ B[N,K]^T   (row-major, bf16 in, fp32 out)
// 128x128 tile, BK=32, 2-stage cp.async pipeline (static smem, <48KB),
// ldmatrix + mma.sync.m16n8k16.bf16.  Next-tile loads issued between the
// last ldmatrix and the final MMA block to overlap DRAM fetch with compute.
// ----------------------------------------------------------------------------
#define BM 128
#define BN 128
#define BK 32
#define SROWB 40          // padded bf16 elems per smem row (64B + 16B pad)

__device__ __forceinline__ uint32_t s2u(const void* p) {
    return (uint32_t)__cvta_generic_to_shared(p);
}
__device__ __forceinline__ void cp16(uint32_t dst, const void* src) {
    asm volatile("cp.async.cg.shared.global [%0], [%1], 16;\n" :: "r"(dst), "l"(src));
}
__device__ __forceinline__ void cp_commit() { asm volatile("cp.async.commit_group;\n"); }
__device__ __forceinline__ void cp_wait1()  { asm volatile("cp.async.wait_group 1;\n"); }
__device__ __forceinline__ void ldsm4(uint32_t& r0, uint32_t& r1, uint32_t& r2, uint32_t& r3,
                                      uint32_t addr) {
    asm volatile("ldmatrix.sync.aligned.m8n8.x4.shared.b16 {%0,%1,%2,%3}, [%4];\n"
                 : "=r"(r0), "=r"(r1), "=r"(r2), "=r"(r3) : "r"(addr));
}
__device__ __forceinline__ void mma_bf16(float c[4], const uint32_t a[4], const uint32_t b[2]) {
    asm volatile(
        "mma.sync.aligned.m16n8k16.row.col.f32.bf16.bf16.f32 "
        "{%0,%1,%2,%3}, {%4,%5,%6,%7}, {%8,%9}, {%0,%1,%2,%3};\n"
        : "+f"(c[0]), "+f"(c[1]), "+f"(c[2]), "+f"(c[3])
        : "r"(a[0]), "r"(a[1]), "r"(a[2]), "r"(a[3]), "r"(b[0]), "r"(b[1]));
}

template<int Kdim, int Ndim, bool EPI>
__device__ __forceinline__ void gemm_tc(const __nv_bfloat16* __restrict__ A,
                                        const __nv_bfloat16* __restrict__ B,
                                        float* __restrict__ Cm,
                                        const float* __restrict__ D,
                                        const float* __restrict__ U)
{
    __shared__ __align__(16) __nv_bfloat16 sA[2][BM * SROWB];
    __shared__ __align__(16) __nv_bfloat16 sB[2][BN * SROWB];

    const int tid  = threadIdx.x;
    const int lane = tid & 31;
    const int warp = tid >> 5;       // 8 warps: 2(m) x 4(n)
    const int wm   = warp >> 2;      // 0..1  -> 64 rows
    const int wn   = warp & 3;       // 0..3  -> 32 cols
    const int m0   = blockIdx.y * BM;
    const int n0   = blockIdx.x * BN;

    // loader: 128 rows x 4 chunks(16B = 8 bf16); 256 thr -> 2 rows / thread
    const int lr0 = tid >> 2;            // 0..63
    const int lc  = (tid & 3) * 8;       // bf16 col 0,8,16,24

    auto load_stage = [&](int s, int k0) {
#pragma unroll
        for (int i = 0; i < 2; i++) {
            int r = lr0 + i * 64;
            cp16(s2u(&sA[s][r * SROWB + lc]), A + (size_t)(m0 + r) * Kdim + k0 + lc);
            cp16(s2u(&sB[s][r * SROWB + lc]), B + (size_t)(n0 + r) * Kdim + k0 + lc);
        }
    };

    const int ldrow = lane & 15;
    const int ldsel = lane >> 4;

    float acc[4][4][4];
#pragma unroll
    for (int i = 0; i < 4; i++)
#pragma unroll
        for (int j = 0; j < 4; j++)
#pragma unroll
            for (int v = 0; v < 4; v++) acc[i][j][v] = 0.0f;

    auto ldsm_frags = [&](int buf, int ks, uint32_t af[4][4], uint32_t bfr[4][2]) {
#pragma unroll
        for (int mt = 0; mt < 4; mt++) {
            uint32_t addr = s2u(&sA[buf][(wm * 64 + mt * 16 + ldrow) * SROWB
                                        + ks * 16 + ldsel * 8]);
            ldsm4(af[mt][0], af[mt][1], af[mt][2], af[mt][3], addr);
        }
#pragma unroll
        for (int pair = 0; pair < 2; pair++) {
            uint32_t q0, q1, q2, q3;
            uint32_t addr = s2u(&sB[buf][(wn * 32 + pair * 16 + ldrow) * SROWB
                                        + ks * 16 + ldsel * 8]);
            ldsm4(q0, q1, q2, q3, addr);
            bfr[pair * 2 + 0][0] = q0;  bfr[pair * 2 + 0][1] = q2;
            bfr[pair * 2 + 1][0] = q1;  bfr[pair * 2 + 1][1] = q3;
        }
    };

    const int Ktiles = Kdim / BK;       // 32 (gemm1) / 16 (gemm2)
    load_stage(0, 0);       cp_commit();
    load_stage(1, BK);      cp_commit();

    for (int kt = 0; kt < Ktiles; kt++) {
        cp_wait1();
        __syncthreads();
        const int buf = kt & 1;

        // ks0: fetch fragments + MMA
        uint32_t af0[4][4], bf0[4][2];
        ldsm_frags(buf, 0, af0, bf0);
#pragma unroll
        for (int mt = 0; mt < 4; mt++)
#pragma unroll
            for (int nt = 0; nt < 4; nt++)
                mma_bf16(acc[mt][nt], af0[mt], bf0[nt]);

        // ks1: fetch fragments (last smem reads of this buffer)
        uint32_t af1[4][4], bf1[4][2];
        ldsm_frags(buf, 1, af1, bf1);
        __syncthreads();                       // all reads of buf complete

        // issue next-next tile loads BEFORE the tail MMA block
        if (kt + 2 < Ktiles) load_stage(buf, (kt + 2) * BK);
        cp_commit();

#pragma unroll
        for (int mt = 0; mt < 4; mt++)
#pragma unroll
            for (int nt = 0; nt < 4; nt++)
                mma_bf16(acc[mt][nt], af1[mt], bf1[nt]);
    }

    // Epilogue: per lane c0:(gid,2t) c1:(gid,2t+1) c2:(gid+8,2t) c3:(gid+8,2t+1)
    const int gid = lane >> 2;
    const int tig = lane & 3;
#pragma unroll
    for (int mt = 0; mt < 4; mt++) {
        int r0 = m0 + wm * 64 + mt * 16 + gid;
        int r1 = r0 + 8;
#pragma unroll
        for (int nt = 0; nt < 4; nt++) {
            int col = n0 + wn * 32 + nt * 8 + tig * 2;
            float c0 = acc[mt][nt][0], c1 = acc[mt][nt][1];
            float c2 = acc[mt][nt][2], c3 = acc[mt][nt][3];
            if (EPI) {
                float d0 = __ldg(&D[col]), d1 = __ldg(&D[col + 1]);
                float2 u0 = *(const float2*)&U[(size_t)r0 * Ndim + col];
                float2 u1 = *(const float2*)&U[(size_t)r1 * Ndim + col];
                c0 = fmaf(d0, u0.x, c0);  c1 = fmaf(d1, u0.y, c1);
                c2 = fmaf(d0, u1.x, c2);  c3 = fmaf(d1, u1.y, c3);
            }
            *(float2*)&Cm[(size_t)r0 * Ndim + col] = make_float2(c0, c1);
            *(float2*)&Cm[(size_t)r1 * Ndim + col] = make_float2(c2, c3);
        }
    }
}

__global__ void __launch_bounds__(256) gemm1_kernel()
{
    gemm_tc<H_DIM, PP_DIM, false>(g_U, g_Bbh, g_X, nullptr, nullptr);
}

__global__ void __launch_bounds__(256) gemm2_kernel(float* __restrict__ out,
                                                    const float* __restrict__ D,
                                                    const float* __restrict__ u)
{
    gemm_tc<PP_DIM, H_DIM, true>(g_Xh, g_C2h, out, D, u);
}

// ----------------------------------------------------------------------------
// Chunked scan: x_t = lam * x_{t-1} + Bu_t
// ----------------------------------------------------------------------------
__global__ void scan_local_kernel()
{
    int p = threadIdx.x;
    int c = blockIdx.x;
    float2 lam = g_lam[p];
    float xr = 0.0f, xi = 0.0f;
    float* base = g_X + (size_t)c * S_CHUNK * PP_DIM;
    if (c == 0) {
        __nv_bfloat16* hb = g_Xh;
#pragma unroll 4
        for (int t = 0; t < S_CHUNK; t++) {
            float br = base[t * PP_DIM + p];
            float bi = base[t * PP_DIM + P_DIM + p];
            float nr = fmaf(lam.x, xr, fmaf(-lam.y, xi, br));
            float ni = fmaf(lam.x, xi, fmaf( lam.y, xr, bi));
            xr = nr; xi = ni;
            hb[t * PP_DIM + p]         = __float2bfloat16_rn(xr);
            hb[t * PP_DIM + P_DIM + p] = __float2bfloat16_rn(xi);
        }
    } else {
#pragma unroll 4
        for (int t = 0; t < S_CHUNK; t++) {
            float br = base[t * PP_DIM + p];
            float bi = base[t * PP_DIM + P_DIM + p];
            float nr = fmaf(lam.x, xr, fmaf(-lam.y, xi, br));
            float ni = fmaf(lam.x, xi, fmaf( lam.y, xr, bi));
            xr = nr; xi = ni;
            base[t * PP_DIM + p]         = xr;
            base[t * PP_DIM + P_DIM + p] = xi;
        }
    }
    g_b[c][p] = make_float2(xr, xi);
}

// Parallel carry scan (Kogge-Stone over chunks).  grid = P_DIM blocks,
// NCHUNK threads.  Replaces the 1-block serial kernel whose 256 dependent
// DRAM loads formed a ~50-90us latency chain.
__global__ void carry_scan_kernel()
{
    __shared__ float2 sa[NCHUNK];
    __shared__ float2 sb[NCHUNK];
    int p = blockIdx.x;
    int c = threadIdx.x;
    float2 lS = g_lamS[p];
    float2 a = lS;                   // per-chunk multiplier lamS
    float2 b = g_b[c][p];
    sa[c] = a; sb[c] = b;
    __syncthreads();
#pragma unroll
    for (int s = 1; s < NCHUNK; s <<= 1) {
        float2 pa, pb;
        bool act = (c >= s);
        if (act) { pa = sa[c - s]; pb = sb[c - s]; }
        __syncthreads();
        if (act) {
            // op(prev, cur): A = a*pa ; b = a*pb + b
            float2 na, nb;
            na.x = a.x * pa.x - a.y * pa.y;
            na.y = a.x * pa.y + a.y * pa.x;
            nb.x = fmaf(a.x, pb.x, fmaf(-a.y, pb.y, b.x));
            nb.y = fmaf(a.x, pb.y, fmaf( a.y, pb.x, b.y));
            a = na; b = nb;
            sa[c] = a; sb[c] = b;
        }
        __syncthreads();
    }
    // prefix entering chunk c = inclusive scan at c-1 (0 for c=0)
    g_pref[c][p] = (c == 0) ? make_float2(0.0f, 0.0f) : sb[c - 1];
}

// x_global[t] = x_local[t] + lam^{t+1} * prefix_c ; write bf16 only
__global__ void fixup_kernel()
{
    int p = threadIdx.x;
    int c = blockIdx.x + 1;
    float2 lam = g_lam[p];
    float2 pf = g_pref[c][p];
    float pwr = lam.x, pwi = lam.y;
    const float* base = g_X + (size_t)c * S_CHUNK * PP_DIM;
    __nv_bfloat16* hb = g_Xh + (size_t)c * S_CHUNK * PP_DIM;
#pragma unroll 4
    for (int t = 0; t < S_CHUNK; t++) {
        float cr = pwr * pf.x - pwi * pf.y;
        float ci = pwr * pf.y + pwi * pf.x;
        hb[t * PP_DIM + p]         = __float2bfloat16_rn(base[t * PP_DIM + p] + cr);
        hb[t * PP_DIM + P_DIM + p] = __float2bfloat16_rn(base[t * PP_DIM + P_DIM + p] + ci);
        float nr = pwr * lam.x - pwi * lam.y;
        float ni = pwr * lam.y + pwi * lam.x;
        pwr = nr; pwi = ni;
    }
}

// ----------------------------------------------------------------------------
// Launch
// ----------------------------------------------------------------------------
extern "C" void kernel_launch(void* const* d_in, const int* in_sizes, int n_in,
                              void* d_out, int out_size)
{
    const float* u   = (const float*)d_in[0];  // (L, H)
    const float* Lre = (const float*)d_in[1];  // (P,)
    const float* Lim = (const float*)d_in[2];  // (P,)
    const float* B   = (const float*)d_in[3];  // (P, H, 2)
    const float* C   = (const float*)d_in[4];  // (H, P, 2)
    const float* D   = (const float*)d_in[5];  // (H,)
    const float* ls  = (const float*)d_in[6];  // (P,)
    float* out = (float*)d_out;                // (L, H)

    prep_kernel<<<1, P_DIM>>>(Lre, Lim, ls);
    make_bbar_kernel<<<P_DIM, H_DIM>>>(B);
    make_c2_kernel<<<H_DIM, P_DIM>>>(C);
    round_u_kernel<<<(L_SEQ * H_DIM / 8) / 256, 256>>>(u);

    // GEMM1: Bu = u @ Bb^T   -> g_X   (M=L, N=512, K=1024)
    gemm1_kernel<<<dim3(PP_DIM / BN, L_SEQ / BM), 256>>>();

    // Scan: g_X (fp32) -> g_Xh (bf16)
    scan_local_kernel<<<NCHUNK, P_DIM>>>();
    carry_scan_kernel<<<P_DIM, NCHUNK>>>();
    fixup_kernel<<<NCHUNK - 1, P_DIM>>>();

    // GEMM2: out = xs @ C2^T + D .* u   (M=L, N=1024, K=512)
    gemm2_kernel<<<dim3(H_DIM / BN, L_SEQ / BM), 256>>>(out, D, u);
}

// round 10
// speedup vs baseline: 4.5850x; 1.1487x over previous
#include <cuda_runtime.h>
#include <cuda_bf16.h>
#include <cstdint>

// Problem constants
#define L_SEQ  16384
#define H_DIM  1024
#define P_DIM  256
#define PP_DIM 512          // 2*P : [re | im] planes
#define NCHUNK 256
#define S_CHUNK 64          // L = NCHUNK * S_CHUNK

// ----------------------------------------------------------------------------
// Device scratch (static globals; no cudaMalloc allowed)
// ----------------------------------------------------------------------------
__device__ float          g_X [(size_t)L_SEQ * PP_DIM];   // Bu (read-only after gemm1)
__device__ __nv_bfloat16  g_Xh[(size_t)L_SEQ * PP_DIM];   // xs rounded to bf16 (gemm2 A)
__device__ __nv_bfloat16  g_U [(size_t)L_SEQ * H_DIM];    // u rounded to bf16 (gemm1 A)
__device__ __nv_bfloat16  g_Bbh[PP_DIM * H_DIM];          // B_bar bf16 [re|im] x H
__device__ __nv_bfloat16  g_C2h[H_DIM * PP_DIM];          // [2*Cr | -2*Ci] bf16
__device__ float2 g_lam[P_DIM];
__device__ float2 g_gamma[P_DIM];
__device__ float2 g_lamS[P_DIM];
__device__ float2 g_b[NCHUNK][P_DIM];
__device__ float2 g_pref[NCHUNK][P_DIM];

// ----------------------------------------------------------------------------
// prep: Lambda_bar, gamma, lam^S (fp32 rounding points match jax; transcendentals
// in double)
// ----------------------------------------------------------------------------
__global__ void prep_kernel(const float* __restrict__ Lre,
                            const float* __restrict__ Lim,
                            const float* __restrict__ log_step)
{
    int p = threadIdx.x;
    float st = expf(log_step[p]);
    float ar = Lre[p] * st;
    float ai = Lim[p] * st;

    double er = exp((double)ar);
    double lr = er * cos((double)ai);
    double li = er * sin((double)ai);
    g_lam[p] = make_float2((float)lr, (float)li);

    double Lr = (double)Lre[p], Li = (double)Lim[p];
    double den = Lr * Lr + Li * Li;
    double nr = lr - 1.0, ni = li;
    g_gamma[p] = make_float2((float)((nr * Lr + ni * Li) / den),
                             (float)((ni * Lr - nr * Li) / den));

    double erS = exp((double)ar * S_CHUNK);
    double aiS = (double)ai * S_CHUNK;
    g_lamS[p] = make_float2((float)(erS * cos(aiS)), (float)(erS * sin(aiS)));
}

// Merged B_bar + C2 rounding.  Blocks 0..P_DIM-1: B_bar rows; blocks
// P_DIM..P_DIM+H_DIM-1: C2 rows.  block = 1024 threads.
__global__ void make_bc_kernel(const float* __restrict__ B,
                               const float* __restrict__ C)
{
    if (blockIdx.x < P_DIM) {
        int p = blockIdx.x;
        int h = threadIdx.x;          // 0..1023
        float2 g = g_gamma[p];
        float br = B[((size_t)p * H_DIM + h) * 2 + 0];
        float bi = B[((size_t)p * H_DIM + h) * 2 + 1];
        g_Bbh[(size_t)p * H_DIM + h]           = __float2bfloat16_rn(g.x * br - g.y * bi);
        g_Bbh[(size_t)(p + P_DIM) * H_DIM + h] = __float2bfloat16_rn(g.x * bi + g.y * br);
    } else {
        int h = blockIdx.x - P_DIM;
        int p = threadIdx.x;
        if (p < P_DIM) {
            g_C2h[(size_t)h * PP_DIM + p]         = __float2bfloat16_rn( 2.0f * C[((size_t)h * P_DIM + p) * 2 + 0]);
            g_C2h[(size_t)h * PP_DIM + P_DIM + p] = __float2bfloat16_rn(-2.0f * C[((size_t)h * P_DIM + p) * 2 + 1]);
        }
    }
}

// u (fp32) -> g_U (bf16, round-to-nearest).  8 elems / thread.
__global__ void round_u_kernel(const float* __restrict__ u)
{
    size_t i = ((size_t)blockIdx.x * blockDim.x + threadIdx.x) * 8;
    float4 a = *(const float4*)(u + i);
    float4 b = *(const float4*)(u + i + 4);
    __nv_bfloat162 h0 = __floats2bfloat162_rn(a.x, a.y);
    __nv_bfloat162 h1 = __floats2bfloat162_rn(a.z, a.w);
    __nv_bfloat162 h2 = __floats2bfloat162_rn(b.x, b.y);
    __nv_bfloat162 h3 = __floats2bfloat162_rn(b.z, b.w);
    uint4 out;
    out.x = *(uint32_t*)&h0;  out.y = *(uint32_t*)&h1;
    out.z = *(uint32_t*)&h2;  out.w = *(uint32_t*)&h3;
    *(uint4*)(g_U + i) = out;
}

// ----------------------------------------------------------------------------
// BF16 tensor-core GEMM:  C[M,N] = A[M,K] @ B[N,K]^T   (row-major, bf16 in, fp32 out)
// 128x128 tile, BK=32, 2-stage cp.async pipeline (static smem, <48KB),
// ldmatrix + mma.sync.m16n8k16.bf16.  Next-tile loads issued between the
// last ldmatrix and the final MMA block to overlap DRAM fetch with compute.
// ----------------------------------------------------------------------------
#define BM 128
#define BN 128
#define BK 32
#define SROWB 40          // padded bf16 elems per smem row (64B + 16B pad)

__device__ __forceinline__ uint32_t s2u(const void* p) {
    return (uint32_t)__cvta_generic_to_shared(p);
}
__device__ __forceinline__ void cp16(uint32_t dst, const void* src) {
    asm volatile("cp.async.cg.shared.global [%0], [%1], 16;\n" :: "r"(dst), "l"(src));
}
__device__ __forceinline__ void cp_commit() { asm volatile("cp.async.commit_group;\n"); }
__device__ __forceinline__ void cp_wait1()  { asm volatile("cp.async.wait_group 1;\n"); }
__device__ __forceinline__ void ldsm4(uint32_t& r0, uint32_t& r1, uint32_t& r2, uint32_t& r3,
                                      uint32_t addr) {
    asm volatile("ldmatrix.sync.aligned.m8n8.x4.shared.b16 {%0,%1,%2,%3}, [%4];\n"
                 : "=r"(r0), "=r"(r1), "=r"(r2), "=r"(r3) : "r"(addr));
}
__device__ __forceinline__ void mma_bf16(float c[4], const uint32_t a[4], const uint32_t b[2]) {
    asm volatile(
        "mma.sync.aligned.m16n8k16.row.col.f32.bf16.bf16.f32 "
        "{%0,%1,%2,%3}, {%4,%5,%6,%7}, {%8,%9}, {%0,%1,%2,%3};\n"
        : "+f"(c[0]), "+f"(c[1]), "+f"(c[2]), "+f"(c[3])
        : "r"(a[0]), "r"(a[1]), "r"(a[2]), "r"(a[3]), "r"(b[0]), "r"(b[1]));
}

template<int Kdim, int Ndim, bool EPI>
__device__ __forceinline__ void gemm_tc(const __nv_bfloat16* __restrict__ A,
                                        const __nv_bfloat16* __restrict__ B,
                                        float* __restrict__ Cm,
                                        const float* __restrict__ D,
                                        const float* __restrict__ U)
{
    __shared__ __align__(16) __nv_bfloat16 sA[2][BM * SROWB];
    __shared__ __align__(16) __nv_bfloat16 sB[2][BN * SROWB];

    const int tid  = threadIdx.x;
    const int lane = tid & 31;
    const int warp = tid >> 5;       // 8 warps: 2(m) x 4(n)
    const int wm   = warp >> 2;      // 0..1  -> 64 rows
    const int wn   = warp & 3;       // 0..3  -> 32 cols
    const int m0   = blockIdx.y * BM;
    const int n0   = blockIdx.x * BN;

    // loader: 128 rows x 4 chunks(16B = 8 bf16); 256 thr -> 2 rows / thread
    const int lr0 = tid >> 2;            // 0..63
    const int lc  = (tid & 3) * 8;       // bf16 col 0,8,16,24

    auto load_stage = [&](int s, int k0) {
#pragma unroll
        for (int i = 0; i < 2; i++) {
            int r = lr0 + i * 64;
            cp16(s2u(&sA[s][r * SROWB + lc]), A + (size_t)(m0 + r) * Kdim + k0 + lc);
            cp16(s2u(&sB[s][r * SROWB + lc]), B + (size_t)(n0 + r) * Kdim + k0 + lc);
        }
    };

    const int ldrow = lane & 15;
    const int ldsel = lane >> 4;

    float acc[4][4][4];
#pragma unroll
    for (int i = 0; i < 4; i++)
#pragma unroll
        for (int j = 0; j < 4; j++)
#pragma unroll
            for (int v = 0; v < 4; v++) acc[i][j][v] = 0.0f;

    auto ldsm_frags = [&](int buf, int ks, uint32_t af[4][4], uint32_t bfr[4][2]) {
#pragma unroll
        for (int mt = 0; mt < 4; mt++) {
            uint32_t addr = s2u(&sA[buf][(wm * 64 + mt * 16 + ldrow) * SROWB
                                        + ks * 16 + ldsel * 8]);
            ldsm4(af[mt][0], af[mt][1], af[mt][2], af[mt][3], addr);
        }
#pragma unroll
        for (int pair = 0; pair < 2; pair++) {
            uint32_t q0, q1, q2, q3;
            uint32_t addr = s2u(&sB[buf][(wn * 32 + pair * 16 + ldrow) * SROWB
                                        + ks * 16 + ldsel * 8]);
            ldsm4(q0, q1, q2, q3, addr);
            bfr[pair * 2 + 0][0] = q0;  bfr[pair * 2 + 0][1] = q2;
            bfr[pair * 2 + 1][0] = q1;  bfr[pair * 2 + 1][1] = q3;
        }
    };

    const int Ktiles = Kdim / BK;       // 32 (gemm1) / 16 (gemm2)
    load_stage(0, 0);       cp_commit();
    load_stage(1, BK);      cp_commit();

    for (int kt = 0; kt < Ktiles; kt++) {
        cp_wait1();
        __syncthreads();
        const int buf = kt & 1;

        // ks0: fetch fragments + MMA
        uint32_t af0[4][4], bf0[4][2];
        ldsm_frags(buf, 0, af0, bf0);
#pragma unroll
        for (int mt = 0; mt < 4; mt++)
#pragma unroll
            for (int nt = 0; nt < 4; nt++)
                mma_bf16(acc[mt][nt], af0[mt], bf0[nt]);

        // ks1: fetch fragments (last smem reads of this buffer)
        uint32_t af1[4][4], bf1[4][2];
        ldsm_frags(buf, 1, af1, bf1);
        __syncthreads();                       // all reads of buf complete

        // issue next-next tile loads BEFORE the tail MMA block
        if (kt + 2 < Ktiles) load_stage(buf, (kt + 2) * BK);
        cp_commit();

#pragma unroll
        for (int mt = 0; mt < 4; mt++)
#pragma unroll
            for (int nt = 0; nt < 4; nt++)
                mma_bf16(acc[mt][nt], af1[mt], bf1[nt]);
    }

    // Epilogue: per lane c0:(gid,2t) c1:(gid,2t+1) c2:(gid+8,2t) c3:(gid+8,2t+1)
    const int gid = lane >> 2;
    const int tig = lane & 3;
#pragma unroll
    for (int mt = 0; mt < 4; mt++) {
        int r0 = m0 + wm * 64 + mt * 16 + gid;
        int r1 = r0 + 8;
#pragma unroll
        for (int nt = 0; nt < 4; nt++) {
            int col = n0 + wn * 32 + nt * 8 + tig * 2;
            float c0 = acc[mt][nt][0], c1 = acc[mt][nt][1];
            float c2 = acc[mt][nt][2], c3 = acc[mt][nt][3];
            if (EPI) {
                float d0 = __ldg(&D[col]), d1 = __ldg(&D[col + 1]);
                float2 u0 = *(const float2*)&U[(size_t)r0 * Ndim + col];
                float2 u1 = *(const float2*)&U[(size_t)r1 * Ndim + col];
                c0 = fmaf(d0, u0.x, c0);  c1 = fmaf(d1, u0.y, c1);
                c2 = fmaf(d0, u1.x, c2);  c3 = fmaf(d1, u1.y, c3);
            }
            *(float2*)&Cm[(size_t)r0 * Ndim + col] = make_float2(c0, c1);
            *(float2*)&Cm[(size_t)r1 * Ndim + col] = make_float2(c2, c3);
        }
    }
}

__global__ void __launch_bounds__(256) gemm1_kernel()
{
    gemm_tc<H_DIM, PP_DIM, false>(g_U, g_Bbh, g_X, nullptr, nullptr);
}

__global__ void __launch_bounds__(256) gemm2_kernel(float* __restrict__ out,
                                                    const float* __restrict__ D,
                                                    const float* __restrict__ u)
{
    gemm_tc<PP_DIM, H_DIM, true>(g_Xh, g_C2h, out, D, u);
}

// ----------------------------------------------------------------------------
// Scan, 3 passes.  g_X (Bu) is READ-ONLY throughout — local states are
// recomputed in pass 2 instead of round-tripping 64 MB through DRAM.
// ----------------------------------------------------------------------------

// Pass 1: per-chunk final state only.
__global__ void chunk_final_kernel()
{
    int p = threadIdx.x;
    int c = blockIdx.x;
    float2 lam = g_lam[p];
    float xr = 0.0f, xi = 0.0f;
    const float* base = g_X + (size_t)c * S_CHUNK * PP_DIM;
#pragma unroll 8
    for (int t = 0; t < S_CHUNK; t++) {
        float br = base[t * PP_DIM + p];
        float bi = base[t * PP_DIM + P_DIM + p];
        float nr = fmaf(lam.x, xr, fmaf(-lam.y, xi, br));
        float ni = fmaf(lam.x, xi, fmaf( lam.y, xr, bi));
        xr = nr; xi = ni;
    }
    g_b[c][p] = make_float2(xr, xi);
}

// Pass 2: Kogge-Stone scan over chunk carries.  grid = P_DIM, block = NCHUNK.
__global__ void carry_scan_kernel()
{
    __shared__ float2 sa[NCHUNK];
    __shared__ float2 sb[NCHUNK];
    int p = blockIdx.x;
    int c = threadIdx.x;
    float2 lS = g_lamS[p];
    float2 a = lS;
    float2 b = g_b[c][p];
    sa[c] = a; sb[c] = b;
    __syncthreads();
#pragma unroll
    for (int s = 1; s < NCHUNK; s <<= 1) {
        float2 pa, pb;
        bool act = (c >= s);
        if (act) { pa = sa[c - s]; pb = sb[c - s]; }
        __syncthreads();
        if (act) {
            float2 na, nb;
            na.x = a.x * pa.x - a.y * pa.y;
            na.y = a.x * pa.y + a.y * pa.x;
            nb.x = fmaf(a.x, pb.x, fmaf(-a.y, pb.y, b.x));
            nb.y = fmaf(a.x, pb.y, fmaf( a.y, pb.x, b.y));
            a = na; b = nb;
            sa[c] = a; sb[c] = b;
        }
        __syncthreads();
    }
    g_pref[c][p] = (c == 0) ? make_float2(0.0f, 0.0f) : sb[c - 1];
}

// Pass 3: rerun local recurrence seeded with the carry; emit bf16 only.
__global__ void scan_write_kernel()
{
    int p = threadIdx.x;
    int c = blockIdx.x;
    float2 lam = g_lam[p];
    float2 pf = g_pref[c][p];
    float xr = pf.x, xi = pf.y;
    const float* base = g_X + (size_t)c * S_CHUNK * PP_DIM;
    __nv_bfloat16* hb = g_Xh + (size_t)c * S_CHUNK * PP_DIM;
#pragma unroll 8
    for (int t = 0; t < S_CHUNK; t++) {
        float br = base[t * PP_DIM + p];
        float bi = base[t * PP_DIM + P_DIM + p];
        float nr = fmaf(lam.x, xr, fmaf(-lam.y, xi, br));
        float ni = fmaf(lam.x, xi, fmaf( lam.y, xr, bi));
        xr = nr; xi = ni;
        hb[t * PP_DIM + p]         = __float2bfloat16_rn(xr);
        hb[t * PP_DIM + P_DIM + p] = __float2bfloat16_rn(xi);
    }
}

// ----------------------------------------------------------------------------
// Launch
// ----------------------------------------------------------------------------
extern "C" void kernel_launch(void* const* d_in, const int* in_sizes, int n_in,
                              void* d_out, int out_size)
{
    const float* u   = (const float*)d_in[0];  // (L, H)
    const float* Lre = (const float*)d_in[1];  // (P,)
    const float* Lim = (const float*)d_in[2];  // (P,)
    const float* B   = (const float*)d_in[3];  // (P, H, 2)
    const float* C   = (const float*)d_in[4];  // (H, P, 2)
    const float* D   = (const float*)d_in[5];  // (H,)
    const float* ls  = (const float*)d_in[6];  // (P,)
    float* out = (float*)d_out;                // (L, H)

    prep_kernel<<<1, P_DIM>>>(Lre, Lim, ls);
    make_bc_kernel<<<P_DIM + H_DIM, H_DIM>>>(B, C);
    round_u_kernel<<<(L_SEQ * H_DIM / 8) / 256, 256>>>(u);

    // GEMM1: Bu = u @ Bb^T   -> g_X   (M=L, N=512, K=1024)
    gemm1_kernel<<<dim3(PP_DIM / BN, L_SEQ / BM), 256>>>();

    // Scan: g_X (fp32, read-only) -> g_Xh (bf16)
    chunk_final_kernel<<<NCHUNK, P_DIM>>>();
    carry_scan_kernel<<<P_DIM, NCHUNK>>>();
    scan_write_kernel<<<NCHUNK, P_DIM>>>();

    // GEMM2: out = xs @ C2^T + D .* u   (M=L, N=1024, K=512)
    gemm2_kernel<<<dim3(H_DIM / BN, L_SEQ / BM), 256>>>(out, D, u);
}